// round 7
// baseline (speedup 1.0000x reference)
#include <cuda_runtime.h>

#define NN 50000
#define NE 600000
#define DD 128
#define GRID 148
#define TPB 1024
#define NT (GRID * TPB)
#define SCAN_G 49                      // ceil(NN / 1024)
#define GTILES ((NN + 31) / 32)        // 1563 GEMM tiles of 32 rows

// ---------------- scratch (static device globals; no allocation) ----------------
__device__ float g_xw[NN * DD];        // x @ W fp32 (L2-resident)
__device__ int   g_degi[NN];           // zero at load; re-zeroed in fill phase
__device__ int   g_start[NN];
__device__ int   g_cur[NN];
__device__ unsigned int g_adj[NE];     // src per edge, CSR by dst
__device__ float g_dinv[NN];
__device__ int   g_bsum[SCAN_G];
__device__ float g_sum[DD];            // zero at load; re-zeroed each run (phase 1)
__device__ float g_sumsq[DD];
__device__ unsigned int g_count;       // barrier arrive count (self-resets to 0)
__device__ volatile unsigned int g_gen;// barrier generation (monotonic)

// ------------- grid-wide barrier (all GRID blocks co-resident: 1 per SM) ---------
__device__ __forceinline__ void grid_sync() {
    __threadfence();                   // make this thread's global writes visible
    __syncthreads();
    if (threadIdx.x == 0) {
        unsigned int gen = g_gen;      // stable until all blocks arrive
        if (atomicAdd(&g_count, 1) == GRID - 1) {
            atomicExch(&g_count, 0);   // reset BEFORE release (ordering via fence)
            __threadfence();
            g_gen = gen + 1;           // release
        } else {
            while (g_gen == gen) __nanosleep(32);
            __threadfence();           // acquire
        }
    }
    __syncthreads();
}

// ---------------- the whole pipeline in one persistent kernel --------------------
__global__ void __launch_bounds__(TPB, 1) mega_kernel(
    const float* __restrict__ x, const float* __restrict__ W,
    const float* __restrict__ bias, const float* __restrict__ gamma,
    const float* __restrict__ beta, const float* __restrict__ u,
    const unsigned int* __restrict__ e, float* __restrict__ z)
{
    extern __shared__ float xs[];          // 8 warpgroups * 32 rows * 128 = 128 KB
    __shared__ float rs[32][DD];           // per-warp BN sum partials (16 KB)
    __shared__ float rq[32][DD];           // per-warp BN sumsq partials (16 KB)
    __shared__ float sc[DD], sh[DD];
    __shared__ int   wsums[32];
    __shared__ int   bpart[2];
    __shared__ int   s64;

    const int tid  = threadIdx.x;
    const int bid  = blockIdx.x;
    const int lane = tid & 31;
    const int wid  = tid >> 5;
    const int gthr = bid * TPB + tid;

    // dtype detect: edge values < 50000 => int64 odd 32-bit words are all zero
    if (tid == 0) {
        int v = 1;
        #pragma unroll
        for (int i = 0; i < 16; i++)
            if (e[2 * i + 1] != 0u) { v = 0; break; }
        s64 = v;
    }
    __syncthreads();
    const int is64 = s64;

    // ================= Phase 0: degree atomics, then GEMM =================
    for (int t = gthr; t < NE; t += NT) {
        int d = is64 ? (int)((const long long*)e)[NE + t] : ((const int*)e)[NE + t];
        atomicAdd(&g_degi[d], 1);
    }

    {   // GEMM: one 32-row tile per warpgroup, fma.rn.f32x2, pack-on-load
        const int wg     = tid >> 7;        // warpgroup 0..7
        const int wg_tid = tid & 127;
        const int cg     = wg_tid & 31;     // column group (4 cols)
        const int rg     = wg_tid >> 5;     // row group (8 rows)
        float* xt = xs + wg * (32 * DD);
        const float4* __restrict__ W4 = (const float4*)W;

        for (int tile = bid * 8 + wg; tile < GTILES; tile += GRID * 8) {
            const int r0 = tile * 32;
            asm volatile("bar.sync %0, 128;" :: "r"(wg + 1));   // protect xt reuse
            for (int idx = wg_tid; idx < 32 * DD; idx += 128) {
                int row = idx >> 7, k = idx & 127;
                xt[idx] = (r0 + row < NN) ? x[(size_t)(r0 + row) * DD + k] : 0.0f;
            }
            asm volatile("bar.sync %0, 128;" :: "r"(wg + 1));

            unsigned long long a[8][2];
            #pragma unroll
            for (int r = 0; r < 8; r++) { a[r][0] = 0ull; a[r][1] = 0ull; }

            #pragma unroll 4
            for (int k = 0; k < DD; k++) {
                float4 w = W4[k * 32 + cg];          // L1-resident (64 KB)
                unsigned long long wxy, wzw;
                asm("mov.b64 %0, {%1,%2};" : "=l"(wxy) : "f"(w.x), "f"(w.y));
                asm("mov.b64 %0, {%1,%2};" : "=l"(wzw) : "f"(w.z), "f"(w.w));
                #pragma unroll
                for (int r = 0; r < 8; r++) {
                    float xv = xt[(rg * 8 + r) * DD + k];   // smem broadcast
                    unsigned long long xd;
                    asm("mov.b64 %0, {%1,%1};" : "=l"(xd) : "f"(xv));
                    asm("fma.rn.f32x2 %0, %1, %2, %0;" : "+l"(a[r][0]) : "l"(xd), "l"(wxy));
                    asm("fma.rn.f32x2 %0, %1, %2, %0;" : "+l"(a[r][1]) : "l"(xd), "l"(wzw));
                }
            }

            float4* __restrict__ out4 = (float4*)g_xw;
            #pragma unroll
            for (int r = 0; r < 8; r++) {
                int row = r0 + rg * 8 + r;
                if (row < NN) {
                    float4 o;
                    asm("mov.b64 {%0,%1}, %2;" : "=f"(o.x), "=f"(o.y) : "l"(a[r][0]));
                    asm("mov.b64 {%0,%1}, %2;" : "=f"(o.z), "=f"(o.w) : "l"(a[r][1]));
                    out4[(size_t)row * 32 + cg] = o;
                }
            }
        }
    }
    grid_sync();

    // ================= Phase 1: scan part 1 (block totals + dinv) =================
    if (bid < SCAN_G) {
        if (bid == 0 && tid < DD) { g_sum[tid] = 0.0f; g_sumsq[tid] = 0.0f; }
        const int i = bid * TPB + tid;
        int d = (i < NN) ? g_degi[i] : 0;
        if (i < NN) g_dinv[i] = rsqrtf((float)d + 1.0f);   // +1 = self loop
        int v = d;
        #pragma unroll
        for (int o = 16; o > 0; o >>= 1) v += __shfl_down_sync(0xffffffffu, v, o);
        if (lane == 0) wsums[wid] = v;
        __syncthreads();
        if (wid == 0) {
            int wv = wsums[lane];
            #pragma unroll
            for (int o = 16; o > 0; o >>= 1) wv += __shfl_down_sync(0xffffffffu, wv, o);
            if (lane == 0) g_bsum[bid] = wv;
        }
    }
    grid_sync();

    // ================= Phase 2: scan part 2 (offsets -> start/cur) =================
    if (bid < SCAN_G) {
        if (tid < 64) {
            int t = (tid < bid) ? g_bsum[tid] : 0;
            #pragma unroll
            for (int o = 16; o > 0; o >>= 1) t += __shfl_down_sync(0xffffffffu, t, o);
            if ((tid & 31) == 0) bpart[tid >> 5] = t;
        }
        const int i = bid * TPB + tid;
        int d = (i < NN) ? g_degi[i] : 0;
        int v = d;
        #pragma unroll
        for (int o = 1; o < 32; o <<= 1) {
            int t = __shfl_up_sync(0xffffffffu, v, o);
            if (lane >= o) v += t;
        }
        if (lane == 31) wsums[wid] = v;
        __syncthreads();
        if (wid == 0) {
            int wv = wsums[lane];
            #pragma unroll
            for (int o = 1; o < 32; o <<= 1) {
                int t = __shfl_up_sync(0xffffffffu, wv, o);
                if (lane >= o) wv += t;
            }
            wsums[lane] = wv;
        }
        __syncthreads();
        if (i < NN) {
            int excl = bpart[0] + bpart[1] + (wid > 0 ? wsums[wid - 1] : 0) + (v - d);
            g_start[i] = excl;
            g_cur[i]   = excl;
        }
    }
    grid_sync();

    // ================= Phase 3: adjacency fill + re-zero degi =================
    for (int t = gthr; t < NN; t += NT) g_degi[t] = 0;   // restore for next replay
    for (int t = gthr; t < NE; t += NT) {
        int s, d;
        if (is64) {
            s = (int)((const long long*)e)[t];
            d = (int)((const long long*)e)[NE + t];
        } else {
            s = ((const int*)e)[t];
            d = ((const int*)e)[NE + t];
        }
        int p = atomicAdd(&g_cur[d], 1);
        g_adj[p] = (unsigned int)s;
    }
    grid_sync();

    // ======= Phase 4: gather (warp/node) + self loop + bias + ReLU + BN stats =======
    {
        const int warpg = bid * 32 + wid;
        const int nwarp = GRID * 32;
        const float4* __restrict__ xw4   = (const float4*)g_xw;
        const float4* __restrict__ bias4 = (const float4*)bias;
        float4*       __restrict__ z4    = (float4*)z;

        const float4 b = bias4[lane];
        float4 ls = make_float4(0.f, 0.f, 0.f, 0.f);
        float4 lq = ls;

        for (int node = warpg; node < NN; node += nwarp) {
            const int beg  = g_start[node];
            const int end  = __ldcg(&g_cur[node]);    // modified by L2 atomics in P3
            const float di = g_dinv[node];

            float4 acc = __ldcg(&xw4[(size_t)node * 32 + lane]);  // self loop (×di²)
            acc.x *= di; acc.y *= di; acc.z *= di; acc.w *= di;

            for (int base = beg; base < end; base += 32) {
                const int cnt = min(32, end - base);
                unsigned int sv = (lane < cnt) ? __ldcg(&g_adj[base + lane]) : 0u;
                float dv = __ldg(&g_dinv[sv]);
                #pragma unroll 4
                for (int j = 0; j < cnt; j++) {
                    unsigned int s = __shfl_sync(0xffffffffu, sv, j);
                    float        n = __shfl_sync(0xffffffffu, dv, j);
                    float4 v = __ldcg(&xw4[(size_t)s * 32 + lane]);
                    acc.x += v.x * n; acc.y += v.y * n;
                    acc.z += v.z * n; acc.w += v.w * n;
                }
            }

            float4 v;
            v.x = fmaxf(acc.x * di + b.x, 0.0f);
            v.y = fmaxf(acc.y * di + b.y, 0.0f);
            v.z = fmaxf(acc.z * di + b.z, 0.0f);
            v.w = fmaxf(acc.w * di + b.w, 0.0f);
            z4[(size_t)node * 32 + lane] = v;

            ls.x += v.x; ls.y += v.y; ls.z += v.z; ls.w += v.w;
            lq.x += v.x * v.x; lq.y += v.y * v.y; lq.z += v.z * v.z; lq.w += v.w * v.w;
        }

        ((float4*)&rs[wid][0])[lane] = ls;
        ((float4*)&rq[wid][0])[lane] = lq;
        __syncthreads();
        if (tid < DD) {
            float s = 0.f, q = 0.f;
            #pragma unroll
            for (int w = 0; w < 32; w++) { s += rs[w][tid]; q += rq[w][tid]; }
            atomicAdd(&g_sum[tid], s);
            atomicAdd(&g_sumsq[tid], q);
        }
    }
    grid_sync();

    // ================= Phase 5: BN params + normalize + dropout =================
    if (tid < DD) {
        float mean = __ldcg(&g_sum[tid]) * (1.0f / NN);     // L2-fresh (atomics)
        float var  = __ldcg(&g_sumsq[tid]) * (1.0f / NN) - mean * mean;
        float s    = gamma[tid] * rsqrtf(var + 1e-5f);
        sc[tid] = s;
        sh[tid] = beta[tid] - mean * s;
    }
    __syncthreads();

    const float inv_keep = 1.0f / 0.9f;
    for (int gid = gthr; gid < NN * 32; gid += NT) {
        int j4 = (gid & 31) * 4;
        float4 v  = ((const float4*)z)[gid];
        float4 uu = ((const float4*)u)[gid];
        float4 r;
        r.x = (uu.x > 0.1f) ? (v.x * sc[j4 + 0] + sh[j4 + 0]) * inv_keep : 0.0f;
        r.y = (uu.y > 0.1f) ? (v.y * sc[j4 + 1] + sh[j4 + 1]) * inv_keep : 0.0f;
        r.z = (uu.z > 0.1f) ? (v.z * sc[j4 + 2] + sh[j4 + 2]) * inv_keep : 0.0f;
        r.w = (uu.w > 0.1f) ? (v.w * sc[j4 + 3] + sh[j4 + 3]) * inv_keep : 0.0f;
        ((float4*)z)[gid] = r;
    }
}

// ---------------- launch: ONE kernel, one graph node ----------------
extern "C" void kernel_launch(void* const* d_in, const int* in_sizes, int n_in,
                              void* d_out, int out_size) {
    const float* x      = (const float*)d_in[0];
    const float* weight = (const float*)d_in[1];
    const float* bias   = (const float*)d_in[2];
    const float* gamma  = (const float*)d_in[3];
    const float* beta   = (const float*)d_in[4];
    const float* drop_u = (const float*)d_in[5];
    const unsigned int* eidx = (const unsigned int*)d_in[6];

    cudaFuncSetAttribute(mega_kernel,
                         cudaFuncAttributeMaxDynamicSharedMemorySize, 131072);
    mega_kernel<<<GRID, TPB, 131072>>>(x, weight, bias, gamma, beta, drop_u,
                                       eidx, (float*)d_out);
}

// round 8
// speedup vs baseline: 1.3585x; 1.3585x over previous
#include <cuda_runtime.h>

#define NN 50000
#define NE 600000
#define DD 128
#define SCAN_B 1024
#define SCAN_G ((NN + SCAN_B - 1) / SCAN_B)   // 49

// ---------------- scratch (static device globals; no allocation) ----------------
__device__ float  g_xw[NN * DD];                // x @ W fp32 (L2-resident)
__device__ int    g_degi[NN];                   // zero at load; fill re-zeroes
__device__ int    g_start[NN];
__device__ int    g_cur[NN];
__device__ unsigned int g_adj[NE];              // src per edge (CSR by dst)
__device__ float  g_dinv[NN];
__device__ int    g_bsum[SCAN_G];
__device__ unsigned int g_ready;                // scan sync; fill resets to 0
__device__ float  g_sum[DD];                    // zeroed in scanf each run
__device__ float  g_sumsq[DD];

// ---- local int64/int32 detection: values < 50000 => int64 odd words all zero ----
__device__ __forceinline__ int detect_is64(const unsigned int* __restrict__ e) {
    int is64 = 1;
    #pragma unroll
    for (int i = 0; i < 16; i++)
        if (e[2 * i + 1] != 0u) { is64 = 0; break; }
    return is64;
}

// ---------------- degree over dst ----------------
__global__ void deg_kernel(const unsigned int* __restrict__ e) {
    __shared__ int s64;
    if (threadIdx.x == 0) s64 = detect_is64(e);
    __syncthreads();
    int t = blockIdx.x * blockDim.x + threadIdx.x;
    if (t >= NE) return;
    int d;
    if (s64) d = (int)((const long long*)e)[NE + t];
    else     d = ((const int*)e)[NE + t];
    atomicAdd(&g_degi[d], 1);
}

// ------- fused scan: dinv + block scan + cross-block sync + start/cur ------------
// 49 blocks, all co-resident (<=148 SMs) -> the spin cannot deadlock.
// g_ready is 0 on entry (static init / reset by fill in the previous run).
__global__ void __launch_bounds__(SCAN_B) scanf_kernel() {
    __shared__ int wsums[32];
    __shared__ int bpart[2];
    const int tid = threadIdx.x, lane = tid & 31, wid = tid >> 5;
    const int bid = blockIdx.x;

    if (bid == 0 && tid < DD) { g_sum[tid] = 0.0f; g_sumsq[tid] = 0.0f; }

    const int i = bid * SCAN_B + tid;
    int d = (i < NN) ? g_degi[i] : 0;
    if (i < NN) g_dinv[i] = rsqrtf((float)d + 1.0f);   // +1 = self loop

    // block-local inclusive scan
    int v = d;
    #pragma unroll
    for (int o = 1; o < 32; o <<= 1) {
        int t = __shfl_up_sync(0xffffffffu, v, o);
        if (lane >= o) v += t;
    }
    if (lane == 31) wsums[wid] = v;
    __syncthreads();
    if (wid == 0) {
        int wv = wsums[lane];
        #pragma unroll
        for (int o = 1; o < 32; o <<= 1) {
            int t = __shfl_up_sync(0xffffffffu, wv, o);
            if (lane >= o) wv += t;
        }
        wsums[lane] = wv;
    }
    __syncthreads();

    // publish block total, then wait for all 49 totals
    if (tid == 0) {
        g_bsum[bid] = wsums[31];
        __threadfence();
        atomicAdd(&g_ready, 1u);
        volatile unsigned int* r = &g_ready;
        while (*r < (unsigned)SCAN_G) __nanosleep(32);
        __threadfence();
    }
    __syncthreads();

    // exclusive sum of predecessor block totals (<=48 values)
    if (tid < 64) {
        int t = (tid < bid) ? g_bsum[tid] : 0;
        #pragma unroll
        for (int o = 16; o > 0; o >>= 1) t += __shfl_down_sync(0xffffffffu, t, o);
        if ((tid & 31) == 0) bpart[tid >> 5] = t;
    }
    __syncthreads();

    if (i < NN) {
        int excl = bpart[0] + bpart[1] + (wid > 0 ? wsums[wid - 1] : 0) + (v - d);
        g_start[i] = excl;
        g_cur[i]   = excl;
    }
}

// -------- adjacency fill; re-zero degi + reset scan sync for next replay ---------
__global__ void fill_kernel(const unsigned int* __restrict__ e) {
    __shared__ int s64;
    if (threadIdx.x == 0) s64 = detect_is64(e);
    __syncthreads();
    int t = blockIdx.x * blockDim.x + threadIdx.x;
    if (t >= NE) return;
    if (t < NN) g_degi[t] = 0;                 // scanf (last reader) already ran
    if (t == 0) g_ready = 0u;                  // reset for next run's scanf
    int s, d;
    if (s64) {
        s = (int)((const long long*)e)[t];
        d = (int)((const long long*)e)[NE + t];
    } else {
        s = ((const int*)e)[t];
        d = ((const int*)e)[NE + t];
    }
    int p = atomicAdd(&g_cur[d], 1);
    g_adj[p] = (unsigned int)s;
}

// ---------------- GEMM: g_xw = x @ W (fp32), packed fma.rn.f32x2 -----------------
__global__ void __launch_bounds__(128) gemm_kernel(const float* __restrict__ x,
                                                   const float* __restrict__ W) {
    __shared__ unsigned long long xs[32][DD];   // 32 KB
    const int tid = threadIdx.x;
    const int r0  = blockIdx.x * 32;

    for (int idx = tid; idx < 32 * DD; idx += 128) {
        int row = idx >> 7, k = idx & 127;
        float v = (r0 + row < NN) ? x[(size_t)(r0 + row) * DD + k] : 0.0f;
        unsigned int u = __float_as_uint(v);
        xs[row][k] = ((unsigned long long)u << 32) | u;
    }
    __syncthreads();

    const int cg = tid & 31;
    const int rg = tid >> 5;
    unsigned long long a[8][2];
    #pragma unroll
    for (int r = 0; r < 8; r++) { a[r][0] = 0ull; a[r][1] = 0ull; }

    const float4* __restrict__ W4 = (const float4*)W;
    #pragma unroll 4
    for (int k = 0; k < DD; k++) {
        float4 w = W4[k * 32 + cg];
        unsigned long long wxy, wzw;
        asm("mov.b64 %0, {%1,%2};" : "=l"(wxy) : "f"(w.x), "f"(w.y));
        asm("mov.b64 %0, {%1,%2};" : "=l"(wzw) : "f"(w.z), "f"(w.w));
        #pragma unroll
        for (int r = 0; r < 8; r++) {
            unsigned long long xd = xs[rg * 8 + r][k];
            asm("fma.rn.f32x2 %0, %1, %2, %0;" : "+l"(a[r][0]) : "l"(xd), "l"(wxy));
            asm("fma.rn.f32x2 %0, %1, %2, %0;" : "+l"(a[r][1]) : "l"(xd), "l"(wzw));
        }
    }

    float4* __restrict__ out4 = (float4*)g_xw;
    #pragma unroll
    for (int r = 0; r < 8; r++) {
        int row = r0 + rg * 8 + r;
        if (row < NN) {
            float4 o;
            asm("mov.b64 {%0,%1}, %2;" : "=f"(o.x), "=f"(o.y) : "l"(a[r][0]));
            asm("mov.b64 {%0,%1}, %2;" : "=f"(o.z), "=f"(o.w) : "l"(a[r][1]));
            out4[(size_t)row * 32 + cg] = o;
        }
    }
}

// ---- gather: TWO nodes per warp (doubled MLP); bias + ReLU + BN stats ------------
__global__ void __launch_bounds__(256) gather_kernel(const float* __restrict__ bias,
                                                     float* __restrict__ z) {
    const int tid   = threadIdx.x;
    const int lane  = tid & 31;
    const int wid   = tid >> 5;
    const int warpg = (blockIdx.x * 256 + tid) >> 5;
    const int nwarp = gridDim.x * 8;

    const float4* __restrict__ xw4   = (const float4*)g_xw;
    const float4* __restrict__ bias4 = (const float4*)bias;
    float4*       __restrict__ z4    = (float4*)z;

    const float4 b = bias4[lane];
    float4 ls = make_float4(0.f, 0.f, 0.f, 0.f);
    float4 lq = ls;

    for (int nA = warpg * 2; nA < NN; nA += nwarp * 2) {
        const int nB = nA + 1;
        const bool hasB = (nB < NN);
        int iA = g_start[nA],              endA = g_cur[nA];
        int iB = hasB ? g_start[nB] : 0,   endB = hasB ? g_cur[nB] : 0;
        const float diA = g_dinv[nA];
        const float diB = hasB ? g_dinv[nB] : 0.0f;

        float4 accA = __ldcg(&xw4[(size_t)nA * 32 + lane]);       // self loop (×di²)
        accA.x *= diA; accA.y *= diA; accA.z *= diA; accA.w *= diA;
        float4 accB = make_float4(0.f, 0.f, 0.f, 0.f);
        if (hasB) {
            accB = __ldcg(&xw4[(size_t)nB * 32 + lane]);
            accB.x *= diB; accB.y *= diB; accB.z *= diB; accB.w *= diB;
        }

        while (iA < endA || iB < endB) {
            int cntA = endA - iA; cntA = cntA > 16 ? 16 : (cntA < 0 ? 0 : cntA);
            int cntB = endB - iB; cntB = cntB > 16 ? 16 : (cntB < 0 ? 0 : cntB);
            unsigned int sv;
            if (lane < 16) sv = (lane < cntA)        ? __ldcg(&g_adj[iA + lane])        : 0u;
            else           sv = ((lane - 16) < cntB) ? __ldcg(&g_adj[iB + (lane - 16)]) : 0u;
            float dv = __ldg(&g_dinv[sv]);
            const int m = cntA > cntB ? cntA : cntB;
            #pragma unroll 2
            for (int j = 0; j < m; j++) {
                unsigned int sa = __shfl_sync(0xffffffffu, sv, j);
                float        na = __shfl_sync(0xffffffffu, dv, j);
                unsigned int sb = __shfl_sync(0xffffffffu, sv, 16 + j);
                float        nb = __shfl_sync(0xffffffffu, dv, 16 + j);
                if (j < cntA) {
                    float4 v = __ldcg(&xw4[(size_t)sa * 32 + lane]);
                    accA.x += v.x * na; accA.y += v.y * na;
                    accA.z += v.z * na; accA.w += v.w * na;
                }
                if (j < cntB) {
                    float4 v = __ldcg(&xw4[(size_t)sb * 32 + lane]);
                    accB.x += v.x * nb; accB.y += v.y * nb;
                    accB.z += v.z * nb; accB.w += v.w * nb;
                }
            }
            iA += cntA; iB += cntB;
        }

        {   // epilogue A
            float4 v;
            v.x = fmaxf(accA.x * diA + b.x, 0.0f);
            v.y = fmaxf(accA.y * diA + b.y, 0.0f);
            v.z = fmaxf(accA.z * diA + b.z, 0.0f);
            v.w = fmaxf(accA.w * diA + b.w, 0.0f);
            z4[(size_t)nA * 32 + lane] = v;
            ls.x += v.x; ls.y += v.y; ls.z += v.z; ls.w += v.w;
            lq.x += v.x * v.x; lq.y += v.y * v.y; lq.z += v.z * v.z; lq.w += v.w * v.w;
        }
        if (hasB) {   // epilogue B
            float4 v;
            v.x = fmaxf(accB.x * diB + b.x, 0.0f);
            v.y = fmaxf(accB.y * diB + b.y, 0.0f);
            v.z = fmaxf(accB.z * diB + b.z, 0.0f);
            v.w = fmaxf(accB.w * diB + b.w, 0.0f);
            z4[(size_t)nB * 32 + lane] = v;
            ls.x += v.x; ls.y += v.y; ls.z += v.z; ls.w += v.w;
            lq.x += v.x * v.x; lq.y += v.y * v.y; lq.z += v.z * v.z; lq.w += v.w * v.w;
        }
    }

    __shared__ float rs[8][DD];
    __shared__ float rq[8][DD];
    ((float4*)&rs[wid][0])[lane] = ls;
    ((float4*)&rq[wid][0])[lane] = lq;
    __syncthreads();
    if (tid < DD) {
        float s = 0.f, q = 0.f;
        #pragma unroll
        for (int w = 0; w < 8; w++) { s += rs[w][tid]; q += rq[w][tid]; }
        atomicAdd(&g_sum[tid], s);
        atomicAdd(&g_sumsq[tid], q);
    }
}

// --------- fused BN params + normalize + dropout (params recomputed/block) -------
__global__ void __launch_bounds__(256) final_kernel(const float* __restrict__ gamma,
                                                    const float* __restrict__ beta,
                                                    const float* __restrict__ u,
                                                    float* __restrict__ z) {
    __shared__ float sc[DD], sh[DD];
    const int tid = threadIdx.x;
    if (tid < DD) {
        float mean = g_sum[tid] * (1.0f / NN);
        float var  = g_sumsq[tid] * (1.0f / NN) - mean * mean;
        float s    = gamma[tid] * rsqrtf(var + 1e-5f);
        sc[tid] = s;
        sh[tid] = beta[tid] - mean * s;
    }
    __syncthreads();

    int gid = blockIdx.x * blockDim.x + tid;
    if (gid >= NN * 32) return;
    int j4 = (gid & 31) * 4;

    float4 v  = ((const float4*)z)[gid];
    float4 uu = ((const float4*)u)[gid];
    const float inv_keep = 1.0f / 0.9f;

    float4 r;
    r.x = (uu.x > 0.1f) ? (v.x * sc[j4 + 0] + sh[j4 + 0]) * inv_keep : 0.0f;
    r.y = (uu.y > 0.1f) ? (v.y * sc[j4 + 1] + sh[j4 + 1]) * inv_keep : 0.0f;
    r.z = (uu.z > 0.1f) ? (v.z * sc[j4 + 2] + sh[j4 + 2]) * inv_keep : 0.0f;
    r.w = (uu.w > 0.1f) ? (v.w * sc[j4 + 3] + sh[j4 + 3]) * inv_keep : 0.0f;
    ((float4*)z)[gid] = r;
}

// ---------------- launch: 6 graph nodes, GEMM forked onto side stream ------------
extern "C" void kernel_launch(void* const* d_in, const int* in_sizes, int n_in,
                              void* d_out, int out_size) {
    const float* x      = (const float*)d_in[0];
    const float* weight = (const float*)d_in[1];
    const float* bias   = (const float*)d_in[2];
    const float* gamma  = (const float*)d_in[3];
    const float* beta   = (const float*)d_in[4];
    const float* drop_u = (const float*)d_in[5];
    const unsigned int* eidx = (const unsigned int*)d_in[6];

    float* z = (float*)d_out;

    static cudaStream_t s2 = nullptr;
    static cudaEvent_t evf = nullptr, evj = nullptr;
    if (s2 == nullptr) {
        cudaStreamCreateWithFlags(&s2, cudaStreamNonBlocking);
        cudaEventCreateWithFlags(&evf, cudaEventDisableTiming);
        cudaEventCreateWithFlags(&evj, cudaEventDisableTiming);
    }

    // fork GEMM (depends only on inputs)
    cudaEventRecord(evf, 0);
    cudaStreamWaitEvent(s2, evf, 0);
    gemm_kernel<<<(NN + 31) / 32, 128, 0, s2>>>(x, weight);
    cudaEventRecord(evj, s2);

    // main chain: edge preprocessing
    deg_kernel<<<(NE + 255) / 256, 256>>>(eidx);
    scanf_kernel<<<SCAN_G, SCAN_B>>>();
    fill_kernel<<<(NE + 255) / 256, 256>>>(eidx);

    // join: gather needs CSR + GEMM output
    cudaStreamWaitEvent(0, evj, 0);
    gather_kernel<<<592, 256>>>(bias, z);
    final_kernel<<<(NN * 32 + 255) / 256, 256>>>(gamma, beta, drop_u, z);
}

// round 9
// speedup vs baseline: 1.4495x; 1.0670x over previous
#include <cuda_runtime.h>
#include <cuda_fp16.h>

#define NN 50000
#define NE 600000
#define DD 128
#define SCAN_B 1024
#define SCAN_G ((NN + SCAN_B - 1) / SCAN_B)   // 49

// ---------------- scratch (static device globals; no allocation) ----------------
__device__ float  g_xw[NN * DD];                // x @ W fp32, 25.6 MB
__device__ __half g_xwh[NN * DD];               // dinv[s] * (x@W)[s] fp16, 12.8 MB
__device__ int    g_degi[NN];                   // zero at load; fill re-zeroes
__device__ int    g_start[NN];
__device__ int    g_cur[NN];
__device__ unsigned int g_adj[NE];              // src per edge (CSR by dst)
__device__ float  g_dinv[NN];
__device__ int    g_bsum[SCAN_G];
__device__ unsigned int g_ready;                // scanf sync; fill resets to 0
__device__ float  g_sum[DD];                    // zeroed in scanf each run
__device__ float  g_sumsq[DD];

// ---- local int64/int32 detection: values < 50000 => int64 odd words all zero ----
__device__ __forceinline__ int detect_is64(const unsigned int* __restrict__ e) {
    int is64 = 1;
    #pragma unroll
    for (int i = 0; i < 16; i++)
        if (e[2 * i + 1] != 0u) { is64 = 0; break; }
    return is64;
}

// ---------------- degree over dst ----------------
__global__ void deg_kernel(const unsigned int* __restrict__ e) {
    __shared__ int s64;
    if (threadIdx.x == 0) s64 = detect_is64(e);
    __syncthreads();
    int t = blockIdx.x * blockDim.x + threadIdx.x;
    if (t >= NE) return;
    int d;
    if (s64) d = (int)((const long long*)e)[NE + t];
    else     d = ((const int*)e)[NE + t];
    atomicAdd(&g_degi[d], 1);
}

// ------- fused scan: dinv + block scan + cross-block sync + start/cur ------------
// 49 blocks, all co-resident (<=148 SMs) -> spin cannot deadlock.
// g_ready is 0 on entry (static init / reset by fill in the previous run).
__global__ void __launch_bounds__(SCAN_B) scanf_kernel() {
    __shared__ int wsums[32];
    __shared__ int bpart[2];
    const int tid = threadIdx.x, lane = tid & 31, wid = tid >> 5;
    const int bid = blockIdx.x;

    if (bid == 0 && tid < DD) { g_sum[tid] = 0.0f; g_sumsq[tid] = 0.0f; }

    const int i = bid * SCAN_B + tid;
    int d = (i < NN) ? g_degi[i] : 0;
    if (i < NN) g_dinv[i] = rsqrtf((float)d + 1.0f);   // +1 = self loop

    int v = d;
    #pragma unroll
    for (int o = 1; o < 32; o <<= 1) {
        int t = __shfl_up_sync(0xffffffffu, v, o);
        if (lane >= o) v += t;
    }
    if (lane == 31) wsums[wid] = v;
    __syncthreads();
    if (wid == 0) {
        int wv = wsums[lane];
        #pragma unroll
        for (int o = 1; o < 32; o <<= 1) {
            int t = __shfl_up_sync(0xffffffffu, wv, o);
            if (lane >= o) wv += t;
        }
        wsums[lane] = wv;
    }
    __syncthreads();

    if (tid == 0) {
        g_bsum[bid] = wsums[31];
        __threadfence();
        atomicAdd(&g_ready, 1u);
        volatile unsigned int* r = &g_ready;
        while (*r < (unsigned)SCAN_G) __nanosleep(32);
        __threadfence();
    }
    __syncthreads();

    if (tid < 64) {
        int t = (tid < bid) ? g_bsum[tid] : 0;
        #pragma unroll
        for (int o = 16; o > 0; o >>= 1) t += __shfl_down_sync(0xffffffffu, t, o);
        if ((tid & 31) == 0) bpart[tid >> 5] = t;
    }
    __syncthreads();

    if (i < NN) {
        int excl = bpart[0] + bpart[1] + (wid > 0 ? wsums[wid - 1] : 0) + (v - d);
        g_start[i] = excl;
        g_cur[i]   = excl;
    }
}

// -------- adjacency fill; re-zero degi + reset scan sync for next replay ---------
__global__ void fill_kernel(const unsigned int* __restrict__ e) {
    __shared__ int s64;
    if (threadIdx.x == 0) s64 = detect_is64(e);
    __syncthreads();
    int t = blockIdx.x * blockDim.x + threadIdx.x;
    if (t >= NE) return;
    if (t < NN) g_degi[t] = 0;                 // scanf (last reader) already ran
    if (t == 0) g_ready = 0u;                  // reset for next run's scanf
    int s, d;
    if (s64) {
        s = (int)((const long long*)e)[t];
        d = (int)((const long long*)e)[NE + t];
    } else {
        s = ((const int*)e)[t];
        d = ((const int*)e)[NE + t];
    }
    int p = atomicAdd(&g_cur[d], 1);
    g_adj[p] = (unsigned int)s;
}

// ---------------- GEMM: g_xw = x @ W (fp32), packed fma.rn.f32x2 -----------------
__global__ void __launch_bounds__(128) gemm_kernel(const float* __restrict__ x,
                                                   const float* __restrict__ W) {
    __shared__ unsigned long long xs[32][DD];   // 32 KB
    const int tid = threadIdx.x;
    const int r0  = blockIdx.x * 32;

    for (int idx = tid; idx < 32 * DD; idx += 128) {
        int row = idx >> 7, k = idx & 127;
        float v = (r0 + row < NN) ? x[(size_t)(r0 + row) * DD + k] : 0.0f;
        unsigned int u = __float_as_uint(v);
        xs[row][k] = ((unsigned long long)u << 32) | u;
    }
    __syncthreads();

    const int cg = tid & 31;
    const int rg = tid >> 5;
    unsigned long long a[8][2];
    #pragma unroll
    for (int r = 0; r < 8; r++) { a[r][0] = 0ull; a[r][1] = 0ull; }

    const float4* __restrict__ W4 = (const float4*)W;
    #pragma unroll 4
    for (int k = 0; k < DD; k++) {
        float4 w = W4[k * 32 + cg];
        unsigned long long wxy, wzw;
        asm("mov.b64 %0, {%1,%2};" : "=l"(wxy) : "f"(w.x), "f"(w.y));
        asm("mov.b64 %0, {%1,%2};" : "=l"(wzw) : "f"(w.z), "f"(w.w));
        #pragma unroll
        for (int r = 0; r < 8; r++) {
            unsigned long long xd = xs[rg * 8 + r][k];
            asm("fma.rn.f32x2 %0, %1, %2, %0;" : "+l"(a[r][0]) : "l"(xd), "l"(wxy));
            asm("fma.rn.f32x2 %0, %1, %2, %0;" : "+l"(a[r][1]) : "l"(xd), "l"(wzw));
        }
    }

    float4* __restrict__ out4 = (float4*)g_xw;
    #pragma unroll
    for (int r = 0; r < 8; r++) {
        int row = r0 + rg * 8 + r;
        if (row < NN) {
            float4 o;
            asm("mov.b64 {%0,%1}, %2;" : "=f"(o.x), "=f"(o.y) : "l"(a[r][0]));
            asm("mov.b64 {%0,%1}, %2;" : "=f"(o.z), "=f"(o.w) : "l"(a[r][1]));
            out4[(size_t)row * 32 + cg] = o;
        }
    }
}

// ------------- prescale: g_xwh[row] = fp16(dinv[row] * g_xw[row]) ----------------
__global__ void __launch_bounds__(256) prescale_kernel() {
    int gid = blockIdx.x * blockDim.x + threadIdx.x;   // NN*32 float4 chunks
    if (gid >= NN * 32) return;
    float di = g_dinv[gid >> 5];
    float4 v = ((const float4*)g_xw)[gid];
    __half2 h01 = __floats2half2_rn(v.x * di, v.y * di);
    __half2 h23 = __floats2half2_rn(v.z * di, v.w * di);
    uint2 u;
    u.x = *(unsigned int*)&h01;
    u.y = *(unsigned int*)&h23;
    ((uint2*)g_xwh)[gid] = u;
}

// ---- gather (R5 winner): warp per node, 2 edges in flight, fp16 rows -------------
__device__ __forceinline__ float2 h2f(unsigned int h) {
    __half2 hh = *(__half2*)&h;
    return __half22float2(hh);
}

__global__ void __launch_bounds__(256) gather_kernel(const float* __restrict__ bias,
                                                     float* __restrict__ z) {
    const int tid   = threadIdx.x;
    const int lane  = tid & 31;
    const int wid   = tid >> 5;
    const int g     = lane >> 4;   // half-warp id (0/1)
    const int hl    = lane & 15;   // lane within half-warp -> cols 8*hl..8*hl+7
    const int warpg = (blockIdx.x * 256 + tid) >> 5;
    const int nwarp = gridDim.x * 8;

    const uint4*  __restrict__ xws   = (const uint4*)g_xwh;   // row = 16 uint4
    const float4* __restrict__ bias4 = (const float4*)bias;
    float4*       __restrict__ z4    = (float4*)z;

    const float4 b0 = bias4[2 * hl];
    const float4 b1 = bias4[2 * hl + 1];
    float ls[8], lq[8];
    #pragma unroll
    for (int k = 0; k < 8; k++) { ls[k] = 0.f; lq[k] = 0.f; }

    for (int node = warpg; node < NN; node += nwarp) {
        const int beg = g_start[node];
        const int end = g_cur[node];
        const float di = g_dinv[node];

        float a[8];
        #pragma unroll
        for (int k = 0; k < 8; k++) a[k] = 0.f;

        // self loop (only half-warp 0 adds it)
        if (g == 0) {
            uint4 r = __ldcg(&xws[(size_t)node * 16 + hl]);
            float2 p0 = h2f(r.x), p1 = h2f(r.y), p2 = h2f(r.z), p3 = h2f(r.w);
            a[0] += p0.x; a[1] += p0.y; a[2] += p1.x; a[3] += p1.y;
            a[4] += p2.x; a[5] += p2.y; a[6] += p3.x; a[7] += p3.y;
        }

        for (int base = beg; base < end; base += 32) {
            const int cnt = min(32, end - base);
            unsigned int sv = (lane < cnt) ? g_adj[base + lane] : 0u;  // coalesced
            #pragma unroll 4
            for (int j = 0; j < cnt; j += 2) {
                int ei = j + g;
                unsigned int sj = __shfl_sync(0xffffffffu, sv, ei & 31);
                if (ei < cnt) {
                    uint4 r = __ldcg(&xws[(size_t)sj * 16 + hl]);
                    float2 p0 = h2f(r.x), p1 = h2f(r.y), p2 = h2f(r.z), p3 = h2f(r.w);
                    a[0] += p0.x; a[1] += p0.y; a[2] += p1.x; a[3] += p1.y;
                    a[4] += p2.x; a[5] += p2.y; a[6] += p3.x; a[7] += p3.y;
                }
            }
        }

        // combine the two half-warps
        #pragma unroll
        for (int k = 0; k < 8; k++) a[k] += __shfl_xor_sync(0xffffffffu, a[k], 16);

        if (g == 0) {
            float4 v0, v1;
            v0.x = fmaxf(a[0] * di + b0.x, 0.0f);
            v0.y = fmaxf(a[1] * di + b0.y, 0.0f);
            v0.z = fmaxf(a[2] * di + b0.z, 0.0f);
            v0.w = fmaxf(a[3] * di + b0.w, 0.0f);
            v1.x = fmaxf(a[4] * di + b1.x, 0.0f);
            v1.y = fmaxf(a[5] * di + b1.y, 0.0f);
            v1.z = fmaxf(a[6] * di + b1.z, 0.0f);
            v1.w = fmaxf(a[7] * di + b1.w, 0.0f);
            z4[(size_t)node * 32 + 2 * hl]     = v0;
            z4[(size_t)node * 32 + 2 * hl + 1] = v1;
            ls[0] += v0.x; ls[1] += v0.y; ls[2] += v0.z; ls[3] += v0.w;
            ls[4] += v1.x; ls[5] += v1.y; ls[6] += v1.z; ls[7] += v1.w;
            lq[0] += v0.x * v0.x; lq[1] += v0.y * v0.y; lq[2] += v0.z * v0.z; lq[3] += v0.w * v0.w;
            lq[4] += v1.x * v1.x; lq[5] += v1.y * v1.y; lq[6] += v1.z * v1.z; lq[7] += v1.w * v1.w;
        }
    }

    __shared__ float rs[8][DD];
    __shared__ float rq[8][DD];
    if (g == 0) {
        float4* prs = (float4*)&rs[wid][hl * 8];
        float4* prq = (float4*)&rq[wid][hl * 8];
        prs[0] = make_float4(ls[0], ls[1], ls[2], ls[3]);
        prs[1] = make_float4(ls[4], ls[5], ls[6], ls[7]);
        prq[0] = make_float4(lq[0], lq[1], lq[2], lq[3]);
        prq[1] = make_float4(lq[4], lq[5], lq[6], lq[7]);
    }
    __syncthreads();
    if (tid < DD) {
        float s = 0.f, q = 0.f;
        #pragma unroll
        for (int w = 0; w < 8; w++) { s += rs[w][tid]; q += rq[w][tid]; }
        atomicAdd(&g_sum[tid], s);
        atomicAdd(&g_sumsq[tid], q);
    }
}

// --------- fused BN params + normalize + dropout (params recomputed/block) -------
__global__ void __launch_bounds__(256) final_kernel(const float* __restrict__ gamma,
                                                    const float* __restrict__ beta,
                                                    const float* __restrict__ u,
                                                    float* __restrict__ z) {
    __shared__ float sc[DD], sh[DD];
    const int tid = threadIdx.x;
    if (tid < DD) {
        float mean = g_sum[tid] * (1.0f / NN);
        float var  = g_sumsq[tid] * (1.0f / NN) - mean * mean;
        float s    = gamma[tid] * rsqrtf(var + 1e-5f);
        sc[tid] = s;
        sh[tid] = beta[tid] - mean * s;
    }
    __syncthreads();

    int gid = blockIdx.x * blockDim.x + tid;
    if (gid >= NN * 32) return;
    int j4 = (gid & 31) * 4;

    float4 v  = ((const float4*)z)[gid];
    float4 uu = ((const float4*)u)[gid];
    const float inv_keep = 1.0f / 0.9f;

    float4 r;
    r.x = (uu.x > 0.1f) ? (v.x * sc[j4 + 0] + sh[j4 + 0]) * inv_keep : 0.0f;
    r.y = (uu.y > 0.1f) ? (v.y * sc[j4 + 1] + sh[j4 + 1]) * inv_keep : 0.0f;
    r.z = (uu.z > 0.1f) ? (v.z * sc[j4 + 2] + sh[j4 + 2]) * inv_keep : 0.0f;
    r.w = (uu.w > 0.1f) ? (v.w * sc[j4 + 3] + sh[j4 + 3]) * inv_keep : 0.0f;
    ((float4*)z)[gid] = r;
}

// ---------------- launch: 7 graph nodes, GEMM+prescale on side stream ------------
extern "C" void kernel_launch(void* const* d_in, const int* in_sizes, int n_in,
                              void* d_out, int out_size) {
    const float* x      = (const float*)d_in[0];
    const float* weight = (const float*)d_in[1];
    const float* bias   = (const float*)d_in[2];
    const float* gamma  = (const float*)d_in[3];
    const float* beta   = (const float*)d_in[4];
    const float* drop_u = (const float*)d_in[5];
    const unsigned int* eidx = (const unsigned int*)d_in[6];

    float* z = (float*)d_out;

    static cudaStream_t s2 = nullptr;
    static cudaEvent_t evf = nullptr, evd = nullptr, evj = nullptr;
    if (s2 == nullptr) {
        cudaStreamCreateWithFlags(&s2, cudaStreamNonBlocking);
        cudaEventCreateWithFlags(&evf, cudaEventDisableTiming);
        cudaEventCreateWithFlags(&evd, cudaEventDisableTiming);
        cudaEventCreateWithFlags(&evj, cudaEventDisableTiming);
    }

    // fork GEMM (depends only on inputs)
    cudaEventRecord(evf, 0);
    cudaStreamWaitEvent(s2, evf, 0);
    gemm_kernel<<<(NN + 31) / 32, 128, 0, s2>>>(x, weight);

    // main chain: edge preprocessing
    deg_kernel<<<(NE + 255) / 256, 256>>>(eidx);
    scanf_kernel<<<SCAN_G, SCAN_B>>>();
    cudaEventRecord(evd, 0);                     // dinv ready
    fill_kernel<<<(NE + 255) / 256, 256>>>(eidx);

    // side stream: prescale needs GEMM + dinv
    cudaStreamWaitEvent(s2, evd, 0);
    prescale_kernel<<<(NN * 32 + 255) / 256, 256, 0, s2>>>();
    cudaEventRecord(evj, s2);

    // join: gather needs CSR + prescaled rows
    cudaStreamWaitEvent(0, evj, 0);
    gather_kernel<<<592, 256>>>(bias, z);
    final_kernel<<<(NN * 32 + 255) / 256, 256>>>(gamma, beta, drop_u, z);
}